// round 6
// baseline (speedup 1.0000x reference)
#include <cuda_runtime.h>
#include <cuda_bf16.h>
#include <math.h>

#define B_  4
#define T_  2048
#define C_  672
#define H_  14
#define D_  48
#define C3_ 2016
#define M_  (B_*T_)    // 8192
#define BHT (B_*H_*T_) // 114688

// ---------------- scratch ----------------
__device__ __nv_bfloat16 g_xb [(size_t)M_*C_];
__device__ __nv_bfloat16 g_wa [(size_t)C_*C3_];
__device__ __nv_bfloat16 g_wp [(size_t)C_*C_];
__device__ __nv_bfloat16 g_qkv[(size_t)M_*C3_];
__device__ __nv_bfloat16 g_q  [(size_t)BHT*D_];
__device__ __nv_bfloat16 g_k  [(size_t)BHT*D_];
__device__ __nv_bfloat16 g_v  [(size_t)BHT*D_];
__device__ __nv_bfloat16 g_y  [(size_t)M_*C_];
__device__ int g_isbf16[3];

__device__ __forceinline__ float rbf(float v) {
    return __bfloat162float(__float2bfloat16(v));
}

// ---------------- input dtype detection (defensive; expect f32) ----------------
__global__ void detect_dtype(const void* buf, int which) {
    __shared__ int cnt;
    if (threadIdx.x == 0) cnt = 0;
    __syncthreads();
    const __nv_bfloat16* hb = (const __nv_bfloat16*)buf;
    int local = 0;
    for (int i = threadIdx.x; i < 4096; i += 256) {
        float v = fabsf(__bfloat162float(hb[i]));
        if (isfinite(v) && v > 1e-5f && v < 1e3f) local++;
    }
    atomicAdd(&cnt, local);
    __syncthreads();
    if (threadIdx.x == 0) g_isbf16[which] = (cnt > 3072);
}

__global__ void cast_input(const void* src, __nv_bfloat16* dst, int n, int which) {
    int i = blockIdx.x * blockDim.x + threadIdx.x;
    if (i >= n) return;
    if (g_isbf16[which])
        dst[i] = ((const __nv_bfloat16*)src)[i];
    else
        dst[i] = __float2bfloat16(((const float*)src)[i]);
}

// ---------------- 64x64 GEMM, f32 accum, bf16 out ----------------
__global__ __launch_bounds__(256)
void gemm_bf16(const __nv_bfloat16* __restrict__ A,
               const __nv_bfloat16* __restrict__ Bm,
               __nv_bfloat16* __restrict__ Cm,
               int M, int N, int K) {
    const int BM = 64, BN = 64, BK = 16, TM = 4, TN = 4;
    __shared__ float As[BK][BM + 1];
    __shared__ float Bs[BK][BN + 1];

    int tx = threadIdx.x % (BN / TN);
    int ty = threadIdx.x / (BN / TN);
    int rowBase = blockIdx.y * BM + ty * TM;
    int colBase = blockIdx.x * BN + tx * TN;

    float acc[TM][TN];
#pragma unroll
    for (int i = 0; i < TM; i++)
#pragma unroll
        for (int j = 0; j < TN; j++) acc[i][j] = 0.f;

    for (int k0 = 0; k0 < K; k0 += BK) {
        for (int i = threadIdx.x; i < BM * BK; i += 256) {
            int r = i / BK, c = i % BK;
            int gr = blockIdx.y * BM + r, gc = k0 + c;
            As[c][r] = (gr < M && gc < K)
                         ? __bfloat162float(A[(size_t)gr * K + gc]) : 0.f;
        }
        for (int i = threadIdx.x; i < BK * BN; i += 256) {
            int r = i / BN, c = i % BN;
            int gr = k0 + r, gc = blockIdx.x * BN + c;
            Bs[r][c] = (gr < K && gc < N)
                         ? __bfloat162float(Bm[(size_t)gr * N + gc]) : 0.f;
        }
        __syncthreads();
#pragma unroll
        for (int kk = 0; kk < BK; kk++) {
            float a[TM], b[TN];
#pragma unroll
            for (int i = 0; i < TM; i++) a[i] = As[kk][ty * TM + i];
#pragma unroll
            for (int j = 0; j < TN; j++) b[j] = Bs[kk][tx * TN + j];
#pragma unroll
            for (int i = 0; i < TM; i++)
#pragma unroll
                for (int j = 0; j < TN; j++) acc[i][j] += a[i] * b[j];
        }
        __syncthreads();
    }
#pragma unroll
    for (int i = 0; i < TM; i++) {
        int r = rowBase + i;
        if (r >= M) continue;
#pragma unroll
        for (int j = 0; j < TN; j++) {
            int c = colBase + j;
            if (c >= N) continue;
            Cm[(size_t)r * N + c] = __float2bfloat16(acc[i][j]);
        }
    }
}

// ---------------- 64x64 GEMM, f32 accum, *** FLOAT32 out *** ----------------
// Output buffer d_out is float32 (harness materializes reference bf16 as f32).
// We store the bf16-rounded value widened to f32.
__global__ __launch_bounds__(256)
void gemm_f32out(const __nv_bfloat16* __restrict__ A,
                 const __nv_bfloat16* __restrict__ Bm,
                 float* __restrict__ Cm,
                 int M, int N, int K) {
    const int BM = 64, BN = 64, BK = 16, TM = 4, TN = 4;
    __shared__ float As[BK][BM + 1];
    __shared__ float Bs[BK][BN + 1];

    int tx = threadIdx.x % (BN / TN);
    int ty = threadIdx.x / (BN / TN);
    int rowBase = blockIdx.y * BM + ty * TM;
    int colBase = blockIdx.x * BN + tx * TN;

    float acc[TM][TN];
#pragma unroll
    for (int i = 0; i < TM; i++)
#pragma unroll
        for (int j = 0; j < TN; j++) acc[i][j] = 0.f;

    for (int k0 = 0; k0 < K; k0 += BK) {
        for (int i = threadIdx.x; i < BM * BK; i += 256) {
            int r = i / BK, c = i % BK;
            int gr = blockIdx.y * BM + r, gc = k0 + c;
            As[c][r] = (gr < M && gc < K)
                         ? __bfloat162float(A[(size_t)gr * K + gc]) : 0.f;
        }
        for (int i = threadIdx.x; i < BK * BN; i += 256) {
            int r = i / BN, c = i % BN;
            int gr = k0 + r, gc = blockIdx.x * BN + c;
            Bs[r][c] = (gr < K && gc < N)
                         ? __bfloat162float(Bm[(size_t)gr * N + gc]) : 0.f;
        }
        __syncthreads();
#pragma unroll
        for (int kk = 0; kk < BK; kk++) {
            float a[TM], b[TN];
#pragma unroll
            for (int i = 0; i < TM; i++) a[i] = As[kk][ty * TM + i];
#pragma unroll
            for (int j = 0; j < TN; j++) b[j] = Bs[kk][tx * TN + j];
#pragma unroll
            for (int i = 0; i < TM; i++)
#pragma unroll
                for (int j = 0; j < TN; j++) acc[i][j] += a[i] * b[j];
        }
        __syncthreads();
    }
#pragma unroll
    for (int i = 0; i < TM; i++) {
        int r = rowBase + i;
        if (r >= M) continue;
#pragma unroll
        for (int j = 0; j < TN; j++) {
            int c = colBase + j;
            if (c >= N) continue;
            Cm[(size_t)r * N + c] = rbf(acc[i][j]);   // bf16-rounded, stored f32
        }
    }
}

// ---------------- split QKV -> [B,H,T,D] ----------------
__global__ void split_qkv(int n) {
    int i = blockIdx.x * blockDim.x + threadIdx.x;
    if (i >= n) return;
    int d  = i % D_;
    int t  = (i / D_) % T_;
    int h  = (i / (D_ * T_)) % H_;
    int b  =  i / (D_ * T_ * H_);
    size_t src = (size_t)(b * T_ + t) * C3_ + h * D_ + d;
    g_q[i] = g_qkv[src];
    g_k[i] = g_qkv[src + C_];
    g_v[i] = g_qkv[src + 2 * C_];
}

// ---------------- attention: 1 thread per (b,h,t), 3 passes ----------------
// Reference-exact rounding:
//  s = bf16(bf16(f32 q.k) * bf16(1/sqrt(48)))
//  keep key iff bf16(k_idx) <= bf16(t)  (reference arange is bf16)
//  ALiBi bias = 0 on every kept entry -> skipped
//  e = bf16(exp(bf16(s-m))); l = bf16(f32-sum e); p = bf16(e/l)
//  y = bf16(f32-sum p*v)
__global__ __launch_bounds__(256)
void attn_naive() {
    int gq = blockIdx.x * blockDim.x + threadIdx.x;
    if (gq >= BHT) return;
    int t  = gq % T_;
    int bh = gq / T_;
    int h  = bh % H_;
    int b  = bh / H_;

    const __nv_bfloat16* Kp = g_k + (size_t)bh * T_ * D_;
    const __nv_bfloat16* Vp = g_v + (size_t)bh * T_ * D_;

    const float scale = rbf(0.14433756729740643f);
    const float rq = rbf((float)t);
    int kend = t + 16; if (kend > T_ - 1) kend = T_ - 1;  // bf16-index leak window

    float q[D_];
#pragma unroll
    for (int d = 0; d < D_; d++)
        q[d] = __bfloat162float(g_q[(size_t)gq * D_ + d]);

    // pass 1: max
    float m = -1e30f;
    for (int k = 0; k <= kend; k++) {
        if (rbf((float)k) <= rq) {
            float acc = 0.f;
            const __nv_bfloat16* kr = Kp + (size_t)k * D_;
#pragma unroll
            for (int d = 0; d < D_; d++)
                acc += __bfloat162float(kr[d]) * q[d];
            float s = rbf(rbf(acc) * scale);
            m = fmaxf(m, s);
        }
    }

    // pass 2: denominator
    float l = 0.f;
    for (int k = 0; k <= kend; k++) {
        if (rbf((float)k) <= rq) {
            float acc = 0.f;
            const __nv_bfloat16* kr = Kp + (size_t)k * D_;
#pragma unroll
            for (int d = 0; d < D_; d++)
                acc += __bfloat162float(kr[d]) * q[d];
            float s = rbf(rbf(acc) * scale);
            l += rbf(__expf(rbf(s - m)));
        }
    }
    const float lb = rbf(l);

    // pass 3: output
    float o[D_];
#pragma unroll
    for (int d = 0; d < D_; d++) o[d] = 0.f;
    for (int k = 0; k <= kend; k++) {
        if (rbf((float)k) <= rq) {
            float acc = 0.f;
            const __nv_bfloat16* kr = Kp + (size_t)k * D_;
#pragma unroll
            for (int d = 0; d < D_; d++)
                acc += __bfloat162float(kr[d]) * q[d];
            float s = rbf(rbf(acc) * scale);
            float e = rbf(__expf(rbf(s - m)));
            float p = rbf(e / lb);
            const __nv_bfloat16* vr = Vp + (size_t)k * D_;
#pragma unroll
            for (int d = 0; d < D_; d++)
                o[d] += p * __bfloat162float(vr[d]);
        }
    }

    size_t orow = (size_t)(b * T_ + t) * C_ + h * D_;
#pragma unroll
    for (int d = 0; d < D_; d++)
        g_y[orow + d] = __float2bfloat16(o[d]);
}

// ---------------- launch ----------------
extern "C" void kernel_launch(void* const* d_in, const int* in_sizes, int n_in,
                              void* d_out, int out_size) {
    const void* x = nullptr; const void* w_attn = nullptr; const void* w_proj = nullptr;
    for (int i = 0; i < n_in; i++) {
        if      (in_sizes[i] == M_ * C_)  x      = d_in[i];
        else if (in_sizes[i] == C_ * C3_) w_attn = d_in[i];
        else if (in_sizes[i] == C_ * C_)  w_proj = d_in[i];
    }
    if (!x || !w_attn || !w_proj) { x = d_in[0]; w_attn = d_in[1]; w_proj = d_in[2]; }
    float* out = (float*)d_out;   // *** output dtype is float32 ***

    __nv_bfloat16 *xb, *wa, *wp, *qkv, *y;
    cudaGetSymbolAddress((void**)&xb,  g_xb);
    cudaGetSymbolAddress((void**)&wa,  g_wa);
    cudaGetSymbolAddress((void**)&wp,  g_wp);
    cudaGetSymbolAddress((void**)&qkv, g_qkv);
    cudaGetSymbolAddress((void**)&y,   g_y);

    const int nx  = M_ * C_;
    const int nwa = C_ * C3_;
    const int nwp = C_ * C_;

    detect_dtype<<<1, 256>>>(x,      0);
    detect_dtype<<<1, 256>>>(w_attn, 1);
    detect_dtype<<<1, 256>>>(w_proj, 2);

    cast_input<<<(nx  + 255) / 256, 256>>>(x,      xb, nx,  0);
    cast_input<<<(nwa + 255) / 256, 256>>>(w_attn, wa, nwa, 1);
    cast_input<<<(nwp + 255) / 256, 256>>>(w_proj, wp, nwp, 2);

    // QKV = Xb @ Wattn : [8192,672] x [672,2016]
    {
        dim3 grid(C3_ / 64 + (C3_ % 64 != 0), M_ / 64);   // 32 x 128
        gemm_bf16<<<grid, 256>>>(xb, wa, qkv, M_, C3_, C_);
    }

    // split to [B,H,T,D]
    {
        int n = BHT * D_;
        split_qkv<<<(n + 255) / 256, 256>>>(n);
    }

    // attention
    attn_naive<<<(BHT + 255) / 256, 256>>>();

    // out(f32) = bf16round( Y @ Wproj ) : [8192,672] x [672,672]
    {
        dim3 grid(C_ / 64 + (C_ % 64 != 0), M_ / 64);     // 11 x 128
        gemm_f32out<<<grid, 256>>>(y, wp, out, M_, C_, C_);
    }
}

// round 7
// speedup vs baseline: 3.2296x; 3.2296x over previous
#include <cuda_runtime.h>
#include <cuda_bf16.h>
#include <math.h>

#define B_  4
#define T_  2048
#define C_  672
#define H_  14
#define D_  48
#define C3_ 2016
#define M_  (B_*T_)    // 8192
#define BHT (B_*H_*T_) // 114688
#define BH_ (B_*H_)    // 56

// ---------------- scratch ----------------
__device__ __nv_bfloat16 g_xb [(size_t)M_*C_];
__device__ __nv_bfloat16 g_wa [(size_t)C_*C3_];
__device__ __nv_bfloat16 g_wp [(size_t)C_*C_];
__device__ __nv_bfloat16 g_qkv[(size_t)M_*C3_];
__device__ __nv_bfloat16 g_q  [(size_t)BHT*D_];
__device__ __nv_bfloat16 g_k  [(size_t)BHT*D_];
__device__ __nv_bfloat16 g_v  [(size_t)BHT*D_];
__device__ __nv_bfloat16 g_y  [(size_t)M_*C_];
__device__ __nv_bfloat16 g_s  [(size_t)BHT*T_];   // 470MB logits (masked = -inf)
__device__ int g_isbf16[3];

__device__ __forceinline__ float rbf(float v) {
    return __bfloat162float(__float2bfloat16(v));
}

// ---------------- input dtype detection (defensive; expect f32) ----------------
__global__ void detect_dtype(const void* buf, int which) {
    __shared__ int cnt;
    if (threadIdx.x == 0) cnt = 0;
    __syncthreads();
    const __nv_bfloat16* hb = (const __nv_bfloat16*)buf;
    int local = 0;
    for (int i = threadIdx.x; i < 4096; i += 256) {
        float v = fabsf(__bfloat162float(hb[i]));
        if (isfinite(v) && v > 1e-5f && v < 1e3f) local++;
    }
    atomicAdd(&cnt, local);
    __syncthreads();
    if (threadIdx.x == 0) g_isbf16[which] = (cnt > 3072);
}

__global__ void cast_input(const void* src, __nv_bfloat16* dst, int n, int which) {
    int i = blockIdx.x * blockDim.x + threadIdx.x;
    if (i >= n) return;
    if (g_isbf16[which])
        dst[i] = ((const __nv_bfloat16*)src)[i];
    else
        dst[i] = __float2bfloat16(((const float*)src)[i]);
}

// ---------------- 64x64 GEMM, f32 accum, bf16 out ----------------
__global__ __launch_bounds__(256)
void gemm_bf16(const __nv_bfloat16* __restrict__ A,
               const __nv_bfloat16* __restrict__ Bm,
               __nv_bfloat16* __restrict__ Cm,
               int M, int N, int K) {
    const int BM = 64, BN = 64, BK = 16, TM = 4, TN = 4;
    __shared__ float As[BK][BM + 1];
    __shared__ float Bs[BK][BN + 1];

    int tx = threadIdx.x % (BN / TN);
    int ty = threadIdx.x / (BN / TN);
    int rowBase = blockIdx.y * BM + ty * TM;
    int colBase = blockIdx.x * BN + tx * TN;

    float acc[TM][TN];
#pragma unroll
    for (int i = 0; i < TM; i++)
#pragma unroll
        for (int j = 0; j < TN; j++) acc[i][j] = 0.f;

    for (int k0 = 0; k0 < K; k0 += BK) {
        for (int i = threadIdx.x; i < BM * BK; i += 256) {
            int r = i / BK, c = i % BK;
            int gr = blockIdx.y * BM + r, gc = k0 + c;
            As[c][r] = (gr < M && gc < K)
                         ? __bfloat162float(A[(size_t)gr * K + gc]) : 0.f;
        }
        for (int i = threadIdx.x; i < BK * BN; i += 256) {
            int r = i / BN, c = i % BN;
            int gr = k0 + r, gc = blockIdx.x * BN + c;
            Bs[r][c] = (gr < K && gc < N)
                         ? __bfloat162float(Bm[(size_t)gr * N + gc]) : 0.f;
        }
        __syncthreads();
#pragma unroll
        for (int kk = 0; kk < BK; kk++) {
            float a[TM], b[TN];
#pragma unroll
            for (int i = 0; i < TM; i++) a[i] = As[kk][ty * TM + i];
#pragma unroll
            for (int j = 0; j < TN; j++) b[j] = Bs[kk][tx * TN + j];
#pragma unroll
            for (int i = 0; i < TM; i++)
#pragma unroll
                for (int j = 0; j < TN; j++) acc[i][j] += a[i] * b[j];
        }
        __syncthreads();
    }
#pragma unroll
    for (int i = 0; i < TM; i++) {
        int r = rowBase + i;
        if (r >= M) continue;
#pragma unroll
        for (int j = 0; j < TN; j++) {
            int c = colBase + j;
            if (c >= N) continue;
            Cm[(size_t)r * N + c] = __float2bfloat16(acc[i][j]);
        }
    }
}

// ---------------- 64x64 GEMM, f32 accum, FLOAT32 out (final proj) -----------
__global__ __launch_bounds__(256)
void gemm_f32out(const __nv_bfloat16* __restrict__ A,
                 const __nv_bfloat16* __restrict__ Bm,
                 float* __restrict__ Cm,
                 int M, int N, int K) {
    const int BM = 64, BN = 64, BK = 16, TM = 4, TN = 4;
    __shared__ float As[BK][BM + 1];
    __shared__ float Bs[BK][BN + 1];

    int tx = threadIdx.x % (BN / TN);
    int ty = threadIdx.x / (BN / TN);
    int rowBase = blockIdx.y * BM + ty * TM;
    int colBase = blockIdx.x * BN + tx * TN;

    float acc[TM][TN];
#pragma unroll
    for (int i = 0; i < TM; i++)
#pragma unroll
        for (int j = 0; j < TN; j++) acc[i][j] = 0.f;

    for (int k0 = 0; k0 < K; k0 += BK) {
        for (int i = threadIdx.x; i < BM * BK; i += 256) {
            int r = i / BK, c = i % BK;
            int gr = blockIdx.y * BM + r, gc = k0 + c;
            As[c][r] = (gr < M && gc < K)
                         ? __bfloat162float(A[(size_t)gr * K + gc]) : 0.f;
        }
        for (int i = threadIdx.x; i < BK * BN; i += 256) {
            int r = i / BN, c = i % BN;
            int gr = k0 + r, gc = blockIdx.x * BN + c;
            Bs[r][c] = (gr < K && gc < N)
                         ? __bfloat162float(Bm[(size_t)gr * N + gc]) : 0.f;
        }
        __syncthreads();
#pragma unroll
        for (int kk = 0; kk < BK; kk++) {
            float a[TM], b[TN];
#pragma unroll
            for (int i = 0; i < TM; i++) a[i] = As[kk][ty * TM + i];
#pragma unroll
            for (int j = 0; j < TN; j++) b[j] = Bs[kk][tx * TN + j];
#pragma unroll
            for (int i = 0; i < TM; i++)
#pragma unroll
                for (int j = 0; j < TN; j++) acc[i][j] += a[i] * b[j];
        }
        __syncthreads();
    }
#pragma unroll
    for (int i = 0; i < TM; i++) {
        int r = rowBase + i;
        if (r >= M) continue;
#pragma unroll
        for (int j = 0; j < TN; j++) {
            int c = colBase + j;
            if (c >= N) continue;
            Cm[(size_t)r * N + c] = rbf(acc[i][j]);
        }
    }
}

// ---------------- split QKV -> [B*H, T, D] ----------------
__global__ void split_qkv(int n) {
    int i = blockIdx.x * blockDim.x + threadIdx.x;
    if (i >= n) return;
    int d  = i % D_;
    int t  = (i / D_) % T_;
    int h  = (i / (D_ * T_)) % H_;
    int b  =  i / (D_ * T_ * H_);
    size_t src = (size_t)(b * T_ + t) * C3_ + h * D_ + d;
    g_q[i] = g_qkv[src];
    g_k[i] = g_qkv[src + C_];
    g_v[i] = g_qkv[src + 2 * C_];
}

// ---------------- QK logits: batched 64x64x48 tile GEMM ----------------
// s[bh][t][k] = bf16( bf16(f32 q.k) * bf16(1/sqrt48) ) for kept keys, else -inf.
// Kept iff bf16(k) <= bf16(t) (reference arange is bf16). Only tiles ct<=rt+1.
__global__ __launch_bounds__(256)
void qk_kernel() {
    int ct = blockIdx.x;   // key tile   0..31
    int rt = blockIdx.y;   // query tile 0..31
    int bh = blockIdx.z;   // 0..55
    if (ct > rt + 1) return;

    __shared__ float Qs[64][49];
    __shared__ float Ks[64][49];

    const __nv_bfloat16* Qp = g_q + ((size_t)bh * T_ + rt * 64) * D_;
    const __nv_bfloat16* Kp = g_k + ((size_t)bh * T_ + ct * 64) * D_;
    for (int i = threadIdx.x; i < 64 * D_; i += 256) {
        int r = i / D_, c = i % D_;
        Qs[r][c] = __bfloat162float(Qp[i]);
        Ks[r][c] = __bfloat162float(Kp[i]);
    }
    __syncthreads();

    int tx = threadIdx.x % 16;   // key group
    int ty = threadIdx.x / 16;   // query group
    float acc[4][4];
#pragma unroll
    for (int i = 0; i < 4; i++)
#pragma unroll
        for (int j = 0; j < 4; j++) acc[i][j] = 0.f;

#pragma unroll
    for (int d = 0; d < D_; d++) {
        float a[4], b[4];
#pragma unroll
        for (int i = 0; i < 4; i++) a[i] = Qs[ty * 4 + i][d];
#pragma unroll
        for (int j = 0; j < 4; j++) b[j] = Ks[tx * 4 + j][d];
#pragma unroll
        for (int i = 0; i < 4; i++)
#pragma unroll
            for (int j = 0; j < 4; j++) acc[i][j] += a[i] * b[j];
    }

    const float scale = rbf(0.14433756729740643f);
#pragma unroll
    for (int i = 0; i < 4; i++) {
        int tq = rt * 64 + ty * 4 + i;
        float rq = rbf((float)tq);
        union { __nv_bfloat16 h[4]; uint2 u; } pk;
#pragma unroll
        for (int j = 0; j < 4; j++) {
            int kk = ct * 64 + tx * 4 + j;
            bool keep = rbf((float)kk) <= rq;
            float sval = rbf(acc[i][j]) * scale;
            pk.h[j] = keep ? __float2bfloat16(sval)
                           : __float2bfloat16(-INFINITY);
        }
        *reinterpret_cast<uint2*>(
            &g_s[((size_t)bh * T_ + tq) * T_ + ct * 64 + tx * 4]) = pk.u;
    }
}

// ---------------- softmax + P*V ----------------
// Thread per query. 3 sweeps over precomputed s row (vectorized).
// Semantics identical to R6: e=bf16(exp(bf16(s-m))), l=f32 sum, lb=bf16(l),
// p=bf16(e/lb), o=f32 sum p*v. Masked entries are -inf -> e=0 -> p=0.
__global__ __launch_bounds__(128)
void softmax_pv_kernel() {
    const int qt = blockIdx.x;          // 0..15 (128 queries each)
    const int bh = blockIdx.y;          // 0..55
    const int t  = qt * 128 + threadIdx.x;

    const size_t srow = ((size_t)bh * T_ + t) * T_;
    const int kend = min(t + 16, T_ - 1);
    const int nt = kend / 64 + 1;                          // this thread's tiles
    const int ntcta = min((qt * 128 + 127 + 16) / 64 + 1, T_ / 64);

    const uint4* sv = reinterpret_cast<const uint4*>(g_s + srow);
    union U8 { uint4 u; __nv_bfloat16 h[8]; };

    // sweep 1: max
    float m = -1e30f;
    const int nvec = nt * 8;            // 8 bf16 per uint4, 8 uint4 per tile
    for (int i = 0; i < nvec; i++) {
        U8 pk; pk.u = sv[i];
#pragma unroll
        for (int jj = 0; jj < 8; jj++)
            m = fmaxf(m, __bfloat162float(pk.h[jj]));
    }

    // sweep 2: denominator
    float l = 0.f;
    for (int i = 0; i < nvec; i++) {
        U8 pk; pk.u = sv[i];
#pragma unroll
        for (int jj = 0; jj < 8; jj++) {
            float s = __bfloat162float(pk.h[jj]);
            l += rbf(__expf(rbf(s - m)));
        }
    }
    const float lb = rbf(l);

    // sweep 3: o = sum p*v with V tile in f32 smem
    __shared__ float Vs[64][D_];
    float o[D_];
#pragma unroll
    for (int d = 0; d < D_; d++) o[d] = 0.f;

    for (int kt = 0; kt < ntcta; kt++) {
        const __nv_bfloat16* Vp = g_v + ((size_t)bh * T_ + kt * 64) * D_;
        for (int i = threadIdx.x; i < 64 * D_; i += 128)
            Vs[i / D_][i % D_] = __bfloat162float(Vp[i]);
        __syncthreads();

        if (kt < nt) {
#pragma unroll 1
            for (int jv = 0; jv < 8; jv++) {
                U8 pk; pk.u = sv[kt * 8 + jv];
#pragma unroll
                for (int jj = 0; jj < 8; jj++) {
                    int j = jv * 8 + jj;
                    float s = __bfloat162float(pk.h[jj]);
                    float e = rbf(__expf(rbf(s - m)));
                    float p = rbf(e / lb);
#pragma unroll
                    for (int d = 0; d < D_; d++)
                        o[d] += p * Vs[j][d];
                }
            }
        }
        __syncthreads();
    }

    const int h = bh % H_;
    const int b = bh / H_;
    size_t orow = (size_t)(b * T_ + t) * C_ + h * D_;
#pragma unroll
    for (int d = 0; d < D_; d++)
        g_y[orow + d] = __float2bfloat16(o[d]);
}

// ---------------- launch ----------------
extern "C" void kernel_launch(void* const* d_in, const int* in_sizes, int n_in,
                              void* d_out, int out_size) {
    const void* x = nullptr; const void* w_attn = nullptr; const void* w_proj = nullptr;
    for (int i = 0; i < n_in; i++) {
        if      (in_sizes[i] == M_ * C_)  x      = d_in[i];
        else if (in_sizes[i] == C_ * C3_) w_attn = d_in[i];
        else if (in_sizes[i] == C_ * C_)  w_proj = d_in[i];
    }
    if (!x || !w_attn || !w_proj) { x = d_in[0]; w_attn = d_in[1]; w_proj = d_in[2]; }
    float* out = (float*)d_out;   // output dtype is float32

    __nv_bfloat16 *xb, *wa, *wp, *qkv, *y;
    cudaGetSymbolAddress((void**)&xb,  g_xb);
    cudaGetSymbolAddress((void**)&wa,  g_wa);
    cudaGetSymbolAddress((void**)&wp,  g_wp);
    cudaGetSymbolAddress((void**)&qkv, g_qkv);
    cudaGetSymbolAddress((void**)&y,   g_y);

    const int nx  = M_ * C_;
    const int nwa = C_ * C3_;
    const int nwp = C_ * C_;

    detect_dtype<<<1, 256>>>(x,      0);
    detect_dtype<<<1, 256>>>(w_attn, 1);
    detect_dtype<<<1, 256>>>(w_proj, 2);

    cast_input<<<(nx  + 255) / 256, 256>>>(x,      xb, nx,  0);
    cast_input<<<(nwa + 255) / 256, 256>>>(w_attn, wa, nwa, 1);
    cast_input<<<(nwp + 255) / 256, 256>>>(w_proj, wp, nwp, 2);

    // QKV = Xb @ Wattn : [8192,672] x [672,2016]
    {
        dim3 grid((C3_ + 63) / 64, M_ / 64);
        gemm_bf16<<<grid, 256>>>(xb, wa, qkv, M_, C3_, C_);
    }

    // split to [B*H, T, D]
    {
        int n = BHT * D_;
        split_qkv<<<(n + 255) / 256, 256>>>(n);
    }

    // logits (causal tiles only)
    {
        dim3 grid(T_ / 64, T_ / 64, BH_);    // 32 x 32 x 56, ~half exit
        qk_kernel<<<grid, 256>>>();
    }

    // softmax + PV
    {
        dim3 grid(T_ / 128, BH_);            // 16 x 56
        softmax_pv_kernel<<<grid, 128>>>();
    }

    // out(f32) = bf16round( Y @ Wproj ) : [8192,672] x [672,672]
    {
        dim3 grid((C_ + 63) / 64, M_ / 64);
        gemm_f32out<<<grid, 256>>>(y, wp, out, M_, C_, C_);
    }
}

// round 8
// speedup vs baseline: 6.6677x; 2.0646x over previous
#include <cuda_runtime.h>
#include <cuda_bf16.h>
#include <math.h>
#include <stdint.h>

#define B_  4
#define T_  2048
#define C_  672
#define H_  14
#define D_  48
#define C3_ 2016
#define M_  (B_*T_)    // 8192
#define BHT (B_*H_*T_) // 114688
#define BH_ (B_*H_)    // 56

// ---------------- scratch ----------------
__device__ __nv_bfloat16 g_xb [(size_t)M_*C_];
__device__ __nv_bfloat16 g_wa [(size_t)C_*C3_];
__device__ __nv_bfloat16 g_wp [(size_t)C_*C_];
__device__ __nv_bfloat16 g_wat[(size_t)C3_*C_];   // w_attn^T [2016][672]
__device__ __nv_bfloat16 g_wpt[(size_t)C_*C_];    // w_proj^T [672][672]
__device__ __nv_bfloat16 g_qkv[(size_t)M_*C3_];
__device__ __nv_bfloat16 g_q  [(size_t)BHT*D_];
__device__ __nv_bfloat16 g_k  [(size_t)BHT*D_];
__device__ __nv_bfloat16 g_v  [(size_t)BHT*D_];
__device__ __nv_bfloat16 g_y  [(size_t)M_*C_];
__device__ __nv_bfloat16 g_s  [(size_t)BHT*T_];   // logits (masked = -inf)
__device__ int g_isbf16[3];

__device__ __forceinline__ float rbf(float v) {
    return __bfloat162float(__float2bfloat16(v));
}

__device__ __forceinline__ void mma16816(float c[4],
        uint32_t a0, uint32_t a1, uint32_t a2, uint32_t a3,
        uint32_t b0, uint32_t b1) {
    asm volatile(
        "mma.sync.aligned.m16n8k16.row.col.f32.bf16.bf16.f32 "
        "{%0,%1,%2,%3}, {%4,%5,%6,%7}, {%8,%9}, {%0,%1,%2,%3};\n"
        : "+f"(c[0]), "+f"(c[1]), "+f"(c[2]), "+f"(c[3])
        : "r"(a0), "r"(a1), "r"(a2), "r"(a3), "r"(b0), "r"(b1));
}

// ---------------- input dtype detection (defensive; expect f32) -------------
__global__ void detect_dtype(const void* buf, int which) {
    __shared__ int cnt;
    if (threadIdx.x == 0) cnt = 0;
    __syncthreads();
    const __nv_bfloat16* hb = (const __nv_bfloat16*)buf;
    int local = 0;
    for (int i = threadIdx.x; i < 4096; i += 256) {
        float v = fabsf(__bfloat162float(hb[i]));
        if (isfinite(v) && v > 1e-5f && v < 1e3f) local++;
    }
    atomicAdd(&cnt, local);
    __syncthreads();
    if (threadIdx.x == 0) g_isbf16[which] = (cnt > 3072);
}

__global__ void cast_input(const void* src, __nv_bfloat16* dst, int n, int which) {
    int i = blockIdx.x * blockDim.x + threadIdx.x;
    if (i >= n) return;
    if (g_isbf16[which])
        dst[i] = ((const __nv_bfloat16*)src)[i];
    else
        dst[i] = __float2bfloat16(((const float*)src)[i]);
}

// ---------------- transpose bf16 [R][C] -> [C][R] ----------------
__global__ void transpose_bf16(const __nv_bfloat16* __restrict__ src,
                               __nv_bfloat16* __restrict__ dst, int R, int C) {
    __shared__ __nv_bfloat16 tile[32][33];
    int x = blockIdx.x * 32 + threadIdx.x;
#pragma unroll
    for (int j = 0; j < 4; j++) {
        int y = blockIdx.y * 32 + threadIdx.y + j * 8;
        if (y < R && x < C) tile[threadIdx.y + j * 8][threadIdx.x] = src[(size_t)y * C + x];
    }
    __syncthreads();
    int tx = blockIdx.y * 32 + threadIdx.x;   // dst col (= src row)
#pragma unroll
    for (int j = 0; j < 4; j++) {
        int ty = blockIdx.x * 32 + threadIdx.y + j * 8;  // dst row (= src col)
        if (ty < C && tx < R) dst[(size_t)ty * R + tx] = tile[threadIdx.x][threadIdx.y + j * 8];
    }
}

// ---------------- HMMA GEMM: C = A[M][K] * Bt[N][K]^T ----------------
// CTA 128x128, 8 warps (2x4), warp 64x32, BK=32, 2-stage reg prefetch.
// EPI 0: bf16 out.  EPI 1: f32 out, value bf16-rounded.
__device__ __forceinline__ uint4 ldg_or_zero(const __nv_bfloat16* p, bool valid) {
    uint4 v = make_uint4(0u, 0u, 0u, 0u);
    if (valid) v = *reinterpret_cast<const uint4*>(p);
    return v;
}

template<int EPI>
__global__ __launch_bounds__(256)
void gemm_hmma(const __nv_bfloat16* __restrict__ A,
               const __nv_bfloat16* __restrict__ Bt,
               void* __restrict__ Cout,
               int M, int N, int K) {
    const int PITCH = 40;
    __shared__ __nv_bfloat16 As[128 * PITCH];
    __shared__ __nv_bfloat16 Bs[128 * PITCH];

    const int tid = threadIdx.x, lane = tid & 31, wid = tid >> 5;
    const int wm = wid >> 2, wn = wid & 3;
    const int rowC = blockIdx.y * 128;
    const int colC = blockIdx.x * 128;

    // staging: thread -> (row = tid/2, 16 bf16 at offset (tid&1)*16)
    const int srow = tid >> 1;
    const int sseg = (tid & 1) * 16;
    const __nv_bfloat16* Ag = A  + (size_t)(rowC + srow) * K + sseg;
    const bool bvalid = (colC + srow) < N;
    const __nv_bfloat16* Bg = Bt + (size_t)(colC + srow) * K + sseg;

    float acc[4][4][4];
#pragma unroll
    for (int mt = 0; mt < 4; mt++)
#pragma unroll
        for (int nt = 0; nt < 4; nt++)
#pragma unroll
            for (int r = 0; r < 4; r++) acc[mt][nt][r] = 0.f;

    const int nit = K / 32;
    uint4 sa0 = *reinterpret_cast<const uint4*>(Ag);
    uint4 sa1 = *reinterpret_cast<const uint4*>(Ag + 8);
    uint4 sb0 = ldg_or_zero(Bg, bvalid);
    uint4 sb1 = ldg_or_zero(Bg + 8, bvalid);

    *reinterpret_cast<uint4*>(As + srow * PITCH + sseg)     = sa0;
    *reinterpret_cast<uint4*>(As + srow * PITCH + sseg + 8) = sa1;
    *reinterpret_cast<uint4*>(Bs + srow * PITCH + sseg)     = sb0;
    *reinterpret_cast<uint4*>(Bs + srow * PITCH + sseg + 8) = sb1;
    __syncthreads();

    for (int it = 0; it < nit; it++) {
        if (it + 1 < nit) {
            const __nv_bfloat16* Ag2 = Ag + (it + 1) * 32;
            const __nv_bfloat16* Bg2 = Bg + (it + 1) * 32;
            sa0 = *reinterpret_cast<const uint4*>(Ag2);
            sa1 = *reinterpret_cast<const uint4*>(Ag2 + 8);
            sb0 = ldg_or_zero(Bg2, bvalid);
            sb1 = ldg_or_zero(Bg2 + 8, bvalid);
        }
#pragma unroll
        for (int ks = 0; ks < 2; ks++) {
            const int kb = ks * 16 + (lane & 3) * 2;
            uint32_t af[4][4];
#pragma unroll
            for (int mt = 0; mt < 4; mt++) {
                const __nv_bfloat16* ab = As + (wm * 64 + mt * 16 + (lane >> 2)) * PITCH + kb;
                af[mt][0] = *reinterpret_cast<const uint32_t*>(ab);
                af[mt][1] = *reinterpret_cast<const uint32_t*>(ab + 8 * PITCH);
                af[mt][2] = *reinterpret_cast<const uint32_t*>(ab + 8);
                af[mt][3] = *reinterpret_cast<const uint32_t*>(ab + 8 * PITCH + 8);
            }
            uint32_t bfr[4][2];
#pragma unroll
            for (int nt = 0; nt < 4; nt++) {
                const __nv_bfloat16* bb = Bs + (wn * 32 + nt * 8 + (lane >> 2)) * PITCH + kb;
                bfr[nt][0] = *reinterpret_cast<const uint32_t*>(bb);
                bfr[nt][1] = *reinterpret_cast<const uint32_t*>(bb + 8);
            }
#pragma unroll
            for (int mt = 0; mt < 4; mt++)
#pragma unroll
                for (int nt = 0; nt < 4; nt++)
                    mma16816(acc[mt][nt], af[mt][0], af[mt][1], af[mt][2], af[mt][3],
                             bfr[nt][0], bfr[nt][1]);
        }
        if (it + 1 < nit) {
            __syncthreads();
            *reinterpret_cast<uint4*>(As + srow * PITCH + sseg)     = sa0;
            *reinterpret_cast<uint4*>(As + srow * PITCH + sseg + 8) = sa1;
            *reinterpret_cast<uint4*>(Bs + srow * PITCH + sseg)     = sb0;
            *reinterpret_cast<uint4*>(Bs + srow * PITCH + sseg + 8) = sb1;
            __syncthreads();
        }
    }

#pragma unroll
    for (int mt = 0; mt < 4; mt++) {
        int r0 = rowC + wm * 64 + mt * 16 + (lane >> 2);
#pragma unroll
        for (int nt = 0; nt < 4; nt++) {
            int c0 = colC + wn * 32 + nt * 8 + (lane & 3) * 2;
            if (c0 >= N) continue;
            if (EPI == 0) {
                __nv_bfloat16* Cb = (__nv_bfloat16*)Cout;
                __nv_bfloat162 p0, p1;
                p0.x = __float2bfloat16(acc[mt][nt][0]);
                p0.y = __float2bfloat16(acc[mt][nt][1]);
                p1.x = __float2bfloat16(acc[mt][nt][2]);
                p1.y = __float2bfloat16(acc[mt][nt][3]);
                *reinterpret_cast<__nv_bfloat162*>(Cb + (size_t)r0 * N + c0)       = p0;
                *reinterpret_cast<__nv_bfloat162*>(Cb + (size_t)(r0 + 8) * N + c0) = p1;
            } else {
                float* Cf = (float*)Cout;
                float2 q0 = make_float2(rbf(acc[mt][nt][0]), rbf(acc[mt][nt][1]));
                float2 q1 = make_float2(rbf(acc[mt][nt][2]), rbf(acc[mt][nt][3]));
                *reinterpret_cast<float2*>(Cf + (size_t)r0 * N + c0)       = q0;
                *reinterpret_cast<float2*>(Cf + (size_t)(r0 + 8) * N + c0) = q1;
            }
        }
    }
}

// ---------------- split QKV -> [B*H, T, D] ----------------
__global__ void split_qkv(int n) {
    int i = blockIdx.x * blockDim.x + threadIdx.x;
    if (i >= n) return;
    int d  = i % D_;
    int t  = (i / D_) % T_;
    int h  = (i / (D_ * T_)) % H_;
    int b  =  i / (D_ * T_ * H_);
    size_t src = (size_t)(b * T_ + t) * C3_ + h * D_ + d;
    g_q[i] = g_qkv[src];
    g_k[i] = g_qkv[src + C_];
    g_v[i] = g_qkv[src + 2 * C_];
}

// ---------------- QK logits via HMMA (batched, causal tiles) ----------------
// s = bf16( bf16(acc) * bf16scale ) if bf16(k) <= bf16(t), else -inf.
__global__ __launch_bounds__(256)
void qk_hmma() {
    int ct = blockIdx.x, rt = blockIdx.y, bh = blockIdx.z;
    if (ct > rt + 1) return;
    const int PITCH = 56;
    __shared__ __nv_bfloat16 Qs[128 * PITCH];
    __shared__ __nv_bfloat16 Ks[128 * PITCH];

    const int tid = threadIdx.x, lane = tid & 31, wid = tid >> 5;
    const int wm = wid >> 2, wn = wid & 3;

    const __nv_bfloat16* Qg = g_q + ((size_t)bh * T_ + rt * 128) * D_;
    const __nv_bfloat16* Kg = g_k + ((size_t)bh * T_ + ct * 128) * D_;
    for (int c = tid; c < 768; c += 256) {   // 128 rows x 6 uint4
        int r = c / 6, s = (c % 6) * 8;
        *reinterpret_cast<uint4*>(Qs + r * PITCH + s) =
            *reinterpret_cast<const uint4*>(Qg + (size_t)r * D_ + s);
        *reinterpret_cast<uint4*>(Ks + r * PITCH + s) =
            *reinterpret_cast<const uint4*>(Kg + (size_t)r * D_ + s);
    }
    __syncthreads();

    float acc[4][4][4];
#pragma unroll
    for (int mt = 0; mt < 4; mt++)
#pragma unroll
        for (int nt = 0; nt < 4; nt++)
#pragma unroll
            for (int r = 0; r < 4; r++) acc[mt][nt][r] = 0.f;

#pragma unroll
    for (int ks = 0; ks < 3; ks++) {
        const int kb = ks * 16 + (lane & 3) * 2;
        uint32_t af[4][4];
#pragma unroll
        for (int mt = 0; mt < 4; mt++) {
            const __nv_bfloat16* ab = Qs + (wm * 64 + mt * 16 + (lane >> 2)) * PITCH + kb;
            af[mt][0] = *reinterpret_cast<const uint32_t*>(ab);
            af[mt][1] = *reinterpret_cast<const uint32_t*>(ab + 8 * PITCH);
            af[mt][2] = *reinterpret_cast<const uint32_t*>(ab + 8);
            af[mt][3] = *reinterpret_cast<const uint32_t*>(ab + 8 * PITCH + 8);
        }
        uint32_t bfr[4][2];
#pragma unroll
        for (int nt = 0; nt < 4; nt++) {
            const __nv_bfloat16* bb = Ks + (wn * 32 + nt * 8 + (lane >> 2)) * PITCH + kb;
            bfr[nt][0] = *reinterpret_cast<const uint32_t*>(bb);
            bfr[nt][1] = *reinterpret_cast<const uint32_t*>(bb + 8);
        }
#pragma unroll
        for (int mt = 0; mt < 4; mt++)
#pragma unroll
            for (int nt = 0; nt < 4; nt++)
                mma16816(acc[mt][nt], af[mt][0], af[mt][1], af[mt][2], af[mt][3],
                         bfr[nt][0], bfr[nt][1]);
    }

    const float scale = rbf(0.14433756729740643f);
    const __nv_bfloat16 NEGINF = __float2bfloat16(-INFINITY);
#pragma unroll
    for (int mt = 0; mt < 4; mt++) {
        int r0 = rt * 128 + wm * 64 + mt * 16 + (lane >> 2);
#pragma unroll
        for (int nt = 0; nt < 4; nt++) {
            int c0 = ct * 128 + wn * 32 + nt * 8 + (lane & 3) * 2;
#pragma unroll
            for (int half = 0; half < 2; half++) {
                int rr = r0 + half * 8;
                float rq = rbf((float)rr);
                __nv_bfloat162 pk;
                float v0 = acc[mt][nt][half * 2 + 0];
                float v1 = acc[mt][nt][half * 2 + 1];
                pk.x = (rbf((float)(c0    )) <= rq) ? __float2bfloat16(rbf(v0) * scale) : NEGINF;
                pk.y = (rbf((float)(c0 + 1)) <= rq) ? __float2bfloat16(rbf(v1) * scale) : NEGINF;
                *reinterpret_cast<__nv_bfloat162*>(
                    &g_s[((size_t)bh * T_ + rr) * T_ + c0]) = pk;
            }
        }
    }
}

// ---------------- softmax + P*V (unchanged from R7) ----------------
__global__ __launch_bounds__(128)
void softmax_pv_kernel() {
    const int qt = blockIdx.x;
    const int bh = blockIdx.y;
    const int t  = qt * 128 + threadIdx.x;

    const size_t srow = ((size_t)bh * T_ + t) * T_;
    const int kend = min(t + 16, T_ - 1);
    const int nt = kend / 64 + 1;
    const int ntcta = min((qt * 128 + 127 + 16) / 64 + 1, T_ / 64);

    const uint4* sv = reinterpret_cast<const uint4*>(g_s + srow);
    union U8 { uint4 u; __nv_bfloat16 h[8]; };

    float m = -1e30f;
    const int nvec = nt * 8;
    for (int i = 0; i < nvec; i++) {
        U8 pk; pk.u = sv[i];
#pragma unroll
        for (int jj = 0; jj < 8; jj++)
            m = fmaxf(m, __bfloat162float(pk.h[jj]));
    }

    float l = 0.f;
    for (int i = 0; i < nvec; i++) {
        U8 pk; pk.u = sv[i];
#pragma unroll
        for (int jj = 0; jj < 8; jj++) {
            float s = __bfloat162float(pk.h[jj]);
            l += rbf(__expf(rbf(s - m)));
        }
    }
    const float lb = rbf(l);

    __shared__ float Vs[64][D_];
    float o[D_];
#pragma unroll
    for (int d = 0; d < D_; d++) o[d] = 0.f;

    for (int kt = 0; kt < ntcta; kt++) {
        const __nv_bfloat16* Vp = g_v + ((size_t)bh * T_ + kt * 64) * D_;
        for (int i = threadIdx.x; i < 64 * D_; i += 128)
            Vs[i / D_][i % D_] = __bfloat162float(Vp[i]);
        __syncthreads();

        if (kt < nt) {
#pragma unroll 1
            for (int jv = 0; jv < 8; jv++) {
                U8 pk; pk.u = sv[kt * 8 + jv];
#pragma unroll
                for (int jj = 0; jj < 8; jj++) {
                    int j = jv * 8 + jj;
                    float s = __bfloat162float(pk.h[jj]);
                    float e = rbf(__expf(rbf(s - m)));
                    float p = rbf(e / lb);
#pragma unroll
                    for (int d = 0; d < D_; d++)
                        o[d] += p * Vs[j][d];
                }
            }
        }
        __syncthreads();
    }

    const int h = bh % H_;
    const int b = bh / H_;
    size_t orow = (size_t)(b * T_ + t) * C_ + h * D_;
#pragma unroll
    for (int d = 0; d < D_; d++)
        g_y[orow + d] = __float2bfloat16(o[d]);
}

// ---------------- launch ----------------
extern "C" void kernel_launch(void* const* d_in, const int* in_sizes, int n_in,
                              void* d_out, int out_size) {
    const void* x = nullptr; const void* w_attn = nullptr; const void* w_proj = nullptr;
    for (int i = 0; i < n_in; i++) {
        if      (in_sizes[i] == M_ * C_)  x      = d_in[i];
        else if (in_sizes[i] == C_ * C3_) w_attn = d_in[i];
        else if (in_sizes[i] == C_ * C_)  w_proj = d_in[i];
    }
    if (!x || !w_attn || !w_proj) { x = d_in[0]; w_attn = d_in[1]; w_proj = d_in[2]; }
    float* out = (float*)d_out;   // output dtype is float32

    __nv_bfloat16 *xb, *wa, *wp, *wat, *wpt, *qkv, *y;
    cudaGetSymbolAddress((void**)&xb,  g_xb);
    cudaGetSymbolAddress((void**)&wa,  g_wa);
    cudaGetSymbolAddress((void**)&wp,  g_wp);
    cudaGetSymbolAddress((void**)&wat, g_wat);
    cudaGetSymbolAddress((void**)&wpt, g_wpt);
    cudaGetSymbolAddress((void**)&qkv, g_qkv);
    cudaGetSymbolAddress((void**)&y,   g_y);

    const int nx  = M_ * C_;
    const int nwa = C_ * C3_;
    const int nwp = C_ * C_;

    detect_dtype<<<1, 256>>>(x,      0);
    detect_dtype<<<1, 256>>>(w_attn, 1);
    detect_dtype<<<1, 256>>>(w_proj, 2);

    cast_input<<<(nx  + 255) / 256, 256>>>(x,      xb, nx,  0);
    cast_input<<<(nwa + 255) / 256, 256>>>(w_attn, wa, nwa, 1);
    cast_input<<<(nwp + 255) / 256, 256>>>(w_proj, wp, nwp, 2);

    // transpose weights: wa [672][2016] -> wat [2016][672]; wp -> wpt
    {
        dim3 blk(32, 8);
        dim3 g1(C3_ / 32, C_ / 32);   // x over cols(2016), y over rows(672)
        transpose_bf16<<<g1, blk>>>(wa, wat, C_, C3_);
        dim3 g2(C_ / 32, C_ / 32);
        transpose_bf16<<<g2, blk>>>(wp, wpt, C_, C_);
    }

    // QKV = Xb @ Wattn : HMMA, Bt = wat
    {
        dim3 grid((C3_ + 127) / 128, M_ / 128);   // 16 x 64
        gemm_hmma<0><<<grid, 256>>>(xb, wat, qkv, M_, C3_, C_);
    }

    // split to [B*H, T, D]
    {
        int n = BHT * D_;
        split_qkv<<<(n + 255) / 256, 256>>>(n);
    }

    // QK logits via HMMA (causal tiles only)
    {
        dim3 grid(T_ / 128, T_ / 128, BH_);       // 16 x 16 x 56
        qk_hmma<<<grid, 256>>>();
    }

    // softmax + PV
    {
        dim3 grid(T_ / 128, BH_);                 // 16 x 56
        softmax_pv_kernel<<<grid, 128>>>();
    }

    // out(f32) = bf16round( Y @ Wproj ) : HMMA, Bt = wpt
    {
        dim3 grid((C_ + 127) / 128, M_ / 128);    // 6 x 64
        gemm_hmma<1><<<grid, 256>>>(y, wpt, out, M_, C_, C_);
    }
}

// round 9
// speedup vs baseline: 13.4325x; 2.0145x over previous
#include <cuda_runtime.h>
#include <cuda_bf16.h>
#include <math.h>
#include <stdint.h>

#define B_  4
#define T_  2048
#define C_  672
#define H_  14
#define D_  48
#define C3_ 2016
#define M_  (B_*T_)    // 8192
#define BHT (B_*H_*T_) // 114688
#define BH_ (B_*H_)    // 56

// ---------------- scratch ----------------
__device__ __nv_bfloat16 g_xb [(size_t)M_*C_];
__device__ __nv_bfloat16 g_wa [(size_t)C_*C3_];
__device__ __nv_bfloat16 g_wp [(size_t)C_*C_];
__device__ __nv_bfloat16 g_wat[(size_t)C3_*C_];   // w_attn^T
__device__ __nv_bfloat16 g_wpt[(size_t)C_*C_];    // w_proj^T
__device__ __nv_bfloat16 g_qkv[(size_t)M_*C3_];
__device__ __nv_bfloat16 g_vt [(size_t)BH_*D_*T_]; // V^T per head [bh][48][2048]
__device__ __nv_bfloat16 g_y  [(size_t)M_*C_];
__device__ __nv_bfloat16 g_s  [(size_t)BHT*T_];   // logits -> e (in place)
__device__ float         g_lb [(size_t)BHT];
__device__ int g_isbf16[3];

__device__ __forceinline__ float rbf(float v) {
    return __bfloat162float(__float2bfloat16(v));
}

__device__ __forceinline__ void mma16816(float c[4],
        uint32_t a0, uint32_t a1, uint32_t a2, uint32_t a3,
        uint32_t b0, uint32_t b1) {
    asm volatile(
        "mma.sync.aligned.m16n8k16.row.col.f32.bf16.bf16.f32 "
        "{%0,%1,%2,%3}, {%4,%5,%6,%7}, {%8,%9}, {%0,%1,%2,%3};\n"
        : "+f"(c[0]), "+f"(c[1]), "+f"(c[2]), "+f"(c[3])
        : "r"(a0), "r"(a1), "r"(a2), "r"(a3), "r"(b0), "r"(b1));
}

// ---------------- input dtype detection (defensive; expect f32) -------------
__global__ void detect_dtype(const void* buf, int which) {
    __shared__ int cnt;
    if (threadIdx.x == 0) cnt = 0;
    __syncthreads();
    const __nv_bfloat16* hb = (const __nv_bfloat16*)buf;
    int local = 0;
    for (int i = threadIdx.x; i < 4096; i += 256) {
        float v = fabsf(__bfloat162float(hb[i]));
        if (isfinite(v) && v > 1e-5f && v < 1e3f) local++;
    }
    atomicAdd(&cnt, local);
    __syncthreads();
    if (threadIdx.x == 0) g_isbf16[which] = (cnt > 3072);
}

// vectorized cast: n divisible by 4
__global__ void cast_input4(const void* src, __nv_bfloat16* dst, int n4, int which) {
    int i = blockIdx.x * blockDim.x + threadIdx.x;
    if (i >= n4) return;
    if (g_isbf16[which]) {
        reinterpret_cast<uint2*>(dst)[i] = reinterpret_cast<const uint2*>(src)[i];
    } else {
        float4 v = reinterpret_cast<const float4*>(src)[i];
        union { __nv_bfloat16 h[4]; uint2 u; } pk;
        pk.h[0] = __float2bfloat16(v.x);
        pk.h[1] = __float2bfloat16(v.y);
        pk.h[2] = __float2bfloat16(v.z);
        pk.h[3] = __float2bfloat16(v.w);
        reinterpret_cast<uint2*>(dst)[i] = pk.u;
    }
}

// ---------------- transpose bf16 [R][C] -> [C][R] ----------------
__global__ void transpose_bf16(const __nv_bfloat16* __restrict__ src,
                               __nv_bfloat16* __restrict__ dst, int R, int C) {
    __shared__ __nv_bfloat16 tile[32][33];
    int x = blockIdx.x * 32 + threadIdx.x;
#pragma unroll
    for (int j = 0; j < 4; j++) {
        int y = blockIdx.y * 32 + threadIdx.y + j * 8;
        if (y < R && x < C) tile[threadIdx.y + j * 8][threadIdx.x] = src[(size_t)y * C + x];
    }
    __syncthreads();
    int tx = blockIdx.y * 32 + threadIdx.x;
#pragma unroll
    for (int j = 0; j < 4; j++) {
        int ty = blockIdx.x * 32 + threadIdx.y + j * 8;
        if (ty < C && tx < R) dst[(size_t)ty * R + tx] = tile[threadIdx.x][threadIdx.y + j * 8];
    }
}

// ---------------- HMMA GEMM: C = A[M][K] * Bt[N][K]^T ----------------
__device__ __forceinline__ uint4 ldg_or_zero(const __nv_bfloat16* p, bool valid) {
    uint4 v = make_uint4(0u, 0u, 0u, 0u);
    if (valid) v = *reinterpret_cast<const uint4*>(p);
    return v;
}

template<int EPI>
__global__ __launch_bounds__(256)
void gemm_hmma(const __nv_bfloat16* __restrict__ A,
               const __nv_bfloat16* __restrict__ Bt,
               void* __restrict__ Cout,
               int M, int N, int K) {
    const int PITCH = 40;
    __shared__ __nv_bfloat16 As[128 * PITCH];
    __shared__ __nv_bfloat16 Bs[128 * PITCH];

    const int tid = threadIdx.x, lane = tid & 31, wid = tid >> 5;
    const int wm = wid >> 2, wn = wid & 3;
    const int rowC = blockIdx.y * 128;
    const int colC = blockIdx.x * 128;

    const int srow = tid >> 1;
    const int sseg = (tid & 1) * 16;
    const __nv_bfloat16* Ag = A  + (size_t)(rowC + srow) * K + sseg;
    const bool bvalid = (colC + srow) < N;
    const __nv_bfloat16* Bg = Bt + (size_t)(colC + srow) * K + sseg;

    float acc[4][4][4];
#pragma unroll
    for (int mt = 0; mt < 4; mt++)
#pragma unroll
        for (int nt = 0; nt < 4; nt++)
#pragma unroll
            for (int r = 0; r < 4; r++) acc[mt][nt][r] = 0.f;

    const int nit = K / 32;
    uint4 sa0 = *reinterpret_cast<const uint4*>(Ag);
    uint4 sa1 = *reinterpret_cast<const uint4*>(Ag + 8);
    uint4 sb0 = ldg_or_zero(Bg, bvalid);
    uint4 sb1 = ldg_or_zero(Bg + 8, bvalid);

    *reinterpret_cast<uint4*>(As + srow * PITCH + sseg)     = sa0;
    *reinterpret_cast<uint4*>(As + srow * PITCH + sseg + 8) = sa1;
    *reinterpret_cast<uint4*>(Bs + srow * PITCH + sseg)     = sb0;
    *reinterpret_cast<uint4*>(Bs + srow * PITCH + sseg + 8) = sb1;
    __syncthreads();

    for (int it = 0; it < nit; it++) {
        if (it + 1 < nit) {
            const __nv_bfloat16* Ag2 = Ag + (it + 1) * 32;
            const __nv_bfloat16* Bg2 = Bg + (it + 1) * 32;
            sa0 = *reinterpret_cast<const uint4*>(Ag2);
            sa1 = *reinterpret_cast<const uint4*>(Ag2 + 8);
            sb0 = ldg_or_zero(Bg2, bvalid);
            sb1 = ldg_or_zero(Bg2 + 8, bvalid);
        }
#pragma unroll
        for (int ks = 0; ks < 2; ks++) {
            const int kb = ks * 16 + (lane & 3) * 2;
            uint32_t af[4][4];
#pragma unroll
            for (int mt = 0; mt < 4; mt++) {
                const __nv_bfloat16* ab = As + (wm * 64 + mt * 16 + (lane >> 2)) * PITCH + kb;
                af[mt][0] = *reinterpret_cast<const uint32_t*>(ab);
                af[mt][1] = *reinterpret_cast<const uint32_t*>(ab + 8 * PITCH);
                af[mt][2] = *reinterpret_cast<const uint32_t*>(ab + 8);
                af[mt][3] = *reinterpret_cast<const uint32_t*>(ab + 8 * PITCH + 8);
            }
            uint32_t bfr[4][2];
#pragma unroll
            for (int nt = 0; nt < 4; nt++) {
                const __nv_bfloat16* bb = Bs + (wn * 32 + nt * 8 + (lane >> 2)) * PITCH + kb;
                bfr[nt][0] = *reinterpret_cast<const uint32_t*>(bb);
                bfr[nt][1] = *reinterpret_cast<const uint32_t*>(bb + 8);
            }
#pragma unroll
            for (int mt = 0; mt < 4; mt++)
#pragma unroll
                for (int nt = 0; nt < 4; nt++)
                    mma16816(acc[mt][nt], af[mt][0], af[mt][1], af[mt][2], af[mt][3],
                             bfr[nt][0], bfr[nt][1]);
        }
        if (it + 1 < nit) {
            __syncthreads();
            *reinterpret_cast<uint4*>(As + srow * PITCH + sseg)     = sa0;
            *reinterpret_cast<uint4*>(As + srow * PITCH + sseg + 8) = sa1;
            *reinterpret_cast<uint4*>(Bs + srow * PITCH + sseg)     = sb0;
            *reinterpret_cast<uint4*>(Bs + srow * PITCH + sseg + 8) = sb1;
            __syncthreads();
        }
    }

#pragma unroll
    for (int mt = 0; mt < 4; mt++) {
        int r0 = rowC + wm * 64 + mt * 16 + (lane >> 2);
#pragma unroll
        for (int nt = 0; nt < 4; nt++) {
            int c0 = colC + wn * 32 + nt * 8 + (lane & 3) * 2;
            if (c0 >= N) continue;
            if (EPI == 0) {
                __nv_bfloat16* Cb = (__nv_bfloat16*)Cout;
                __nv_bfloat162 p0, p1;
                p0.x = __float2bfloat16(acc[mt][nt][0]);
                p0.y = __float2bfloat16(acc[mt][nt][1]);
                p1.x = __float2bfloat16(acc[mt][nt][2]);
                p1.y = __float2bfloat16(acc[mt][nt][3]);
                *reinterpret_cast<__nv_bfloat162*>(Cb + (size_t)r0 * N + c0)       = p0;
                *reinterpret_cast<__nv_bfloat162*>(Cb + (size_t)(r0 + 8) * N + c0) = p1;
            } else {
                float* Cf = (float*)Cout;
                float2 q0 = make_float2(rbf(acc[mt][nt][0]), rbf(acc[mt][nt][1]));
                float2 q1 = make_float2(rbf(acc[mt][nt][2]), rbf(acc[mt][nt][3]));
                *reinterpret_cast<float2*>(Cf + (size_t)r0 * N + c0)       = q0;
                *reinterpret_cast<float2*>(Cf + (size_t)(r0 + 8) * N + c0) = q1;
            }
        }
    }
}

// ---------------- V^T per head: g_vt[bh][d][t] ----------------
__global__ __launch_bounds__(256)
void vt_kernel() {
    int tt = blockIdx.x, bh = blockIdx.y;
    int b = bh / H_, h = bh % H_;
    __shared__ __nv_bfloat16 tile[64][56];   // pitch 56 (112B, 16B-aligned)
    for (int i = threadIdx.x; i < 64 * 6; i += 256) {
        int r = i / 6, s = (i % 6) * 8;
        *reinterpret_cast<uint4*>(&tile[r][s]) =
            *reinterpret_cast<const uint4*>(
                &g_qkv[(size_t)(b * T_ + tt * 64 + r) * C3_ + 2 * C_ + h * D_ + s]);
    }
    __syncthreads();
    for (int i = threadIdx.x; i < D_ * 64; i += 256) {
        int d = i / 64, t = i % 64;
        g_vt[((size_t)bh * D_ + d) * T_ + tt * 64 + t] = tile[t][d];
    }
}

// ---------------- QK logits via HMMA (reads g_qkv directly) ----------------
__global__ __launch_bounds__(256)
void qk_hmma() {
    int ct = blockIdx.x, rt = blockIdx.y, bh = blockIdx.z;
    if (ct > rt + 1) return;
    int b = bh / H_, h = bh % H_;
    const int PITCH = 56;
    __shared__ __nv_bfloat16 Qs[128 * PITCH];
    __shared__ __nv_bfloat16 Ks[128 * PITCH];

    const int tid = threadIdx.x, lane = tid & 31, wid = tid >> 5;
    const int wm = wid >> 2, wn = wid & 3;

    const __nv_bfloat16* Qg = g_qkv + (size_t)(b * T_ + rt * 128) * C3_ + h * D_;
    const __nv_bfloat16* Kg = g_qkv + (size_t)(b * T_ + ct * 128) * C3_ + C_ + h * D_;
    for (int c = tid; c < 768; c += 256) {
        int r = c / 6, s = (c % 6) * 8;
        *reinterpret_cast<uint4*>(Qs + r * PITCH + s) =
            *reinterpret_cast<const uint4*>(Qg + (size_t)r * C3_ + s);
        *reinterpret_cast<uint4*>(Ks + r * PITCH + s) =
            *reinterpret_cast<const uint4*>(Kg + (size_t)r * C3_ + s);
    }
    __syncthreads();

    float acc[4][4][4];
#pragma unroll
    for (int mt = 0; mt < 4; mt++)
#pragma unroll
        for (int nt = 0; nt < 4; nt++)
#pragma unroll
            for (int r = 0; r < 4; r++) acc[mt][nt][r] = 0.f;

#pragma unroll
    for (int ks = 0; ks < 3; ks++) {
        const int kb = ks * 16 + (lane & 3) * 2;
        uint32_t af[4][4];
#pragma unroll
        for (int mt = 0; mt < 4; mt++) {
            const __nv_bfloat16* ab = Qs + (wm * 64 + mt * 16 + (lane >> 2)) * PITCH + kb;
            af[mt][0] = *reinterpret_cast<const uint32_t*>(ab);
            af[mt][1] = *reinterpret_cast<const uint32_t*>(ab + 8 * PITCH);
            af[mt][2] = *reinterpret_cast<const uint32_t*>(ab + 8);
            af[mt][3] = *reinterpret_cast<const uint32_t*>(ab + 8 * PITCH + 8);
        }
        uint32_t bfr[4][2];
#pragma unroll
        for (int nt = 0; nt < 4; nt++) {
            const __nv_bfloat16* bb = Ks + (wn * 32 + nt * 8 + (lane >> 2)) * PITCH + kb;
            bfr[nt][0] = *reinterpret_cast<const uint32_t*>(bb);
            bfr[nt][1] = *reinterpret_cast<const uint32_t*>(bb + 8);
        }
#pragma unroll
        for (int mt = 0; mt < 4; mt++)
#pragma unroll
            for (int nt = 0; nt < 4; nt++)
                mma16816(acc[mt][nt], af[mt][0], af[mt][1], af[mt][2], af[mt][3],
                         bfr[nt][0], bfr[nt][1]);
    }

    const float scale = rbf(0.14433756729740643f);
    const __nv_bfloat16 NEGINF = __float2bfloat16(-INFINITY);
#pragma unroll
    for (int mt = 0; mt < 4; mt++) {
        int r0 = rt * 128 + wm * 64 + mt * 16 + (lane >> 2);
#pragma unroll
        for (int nt = 0; nt < 4; nt++) {
            int c0 = ct * 128 + wn * 32 + nt * 8 + (lane & 3) * 2;
#pragma unroll
            for (int half = 0; half < 2; half++) {
                int rr = r0 + half * 8;
                float rq = rbf((float)rr);
                __nv_bfloat162 pk;
                float v0 = acc[mt][nt][half * 2 + 0];
                float v1 = acc[mt][nt][half * 2 + 1];
                pk.x = (rbf((float)(c0    )) <= rq) ? __float2bfloat16(rbf(v0) * scale) : NEGINF;
                pk.y = (rbf((float)(c0 + 1)) <= rq) ? __float2bfloat16(rbf(v1) * scale) : NEGINF;
                *reinterpret_cast<__nv_bfloat162*>(
                    &g_s[((size_t)bh * T_ + rr) * T_ + c0]) = pk;
            }
        }
    }
}

// ---------------- softmax: warp per row; s -> e in place; lb out ------------
__global__ __launch_bounds__(128)
void softmax_es() {
    const int wid = threadIdx.x >> 5, lane = threadIdx.x & 31;
    const int r = blockIdx.x * 4 + wid;        // row over BHT
    const int t = r & (T_ - 1);
    const int qt = t >> 7;
    const int ncov = min(2 * qt + 3, 32);      // tiles of 64 (uniform per qt)
    const int nvec = ncov * 8;                 // uint4 count

    uint4* sv = reinterpret_cast<uint4*>(g_s + (size_t)r * T_);
    union U8 { uint4 u; __nv_bfloat16 h[8]; };

    float m = -1e30f;
    for (int i = lane; i < nvec; i += 32) {
        U8 pk; pk.u = sv[i];
#pragma unroll
        for (int j = 0; j < 8; j++) m = fmaxf(m, __bfloat162float(pk.h[j]));
    }
#pragma unroll
    for (int off = 16; off; off >>= 1)
        m = fmaxf(m, __shfl_xor_sync(0xffffffffu, m, off));

    float l = 0.f;
    for (int i = lane; i < nvec; i += 32) {
        U8 pk; pk.u = sv[i];
        U8 eo;
#pragma unroll
        for (int j = 0; j < 8; j++) {
            float s = __bfloat162float(pk.h[j]);
            float e = rbf(__expf(rbf(s - m)));
            l += e;
            eo.h[j] = __float2bfloat16(e);
        }
        sv[i] = eo.u;
    }
#pragma unroll
    for (int off = 16; off; off >>= 1)
        l += __shfl_xor_sync(0xffffffffu, l, off);

    if (lane == 0) g_lb[r] = rbf(l);
}

// ---------------- PV via HMMA: O[128 x 48] = P * V per (qt, bh) -------------
__global__ __launch_bounds__(128)
void pv_hmma() {
    const int qt = blockIdx.x, bh = blockIdx.y;
    const int b = bh / H_, h = bh % H_;
    const int PITCH = 40;
    __shared__ __nv_bfloat16 Ps[128 * PITCH];
    __shared__ __nv_bfloat16 Vs[48 * PITCH];

    const int tid = threadIdx.x, lane = tid & 31, wid = tid >> 5;
    const int rowg = qt * 128 + tid;  // this thread's staging row (query)
    const float inv = 1.0f / g_lb[(size_t)bh * T_ + rowg];

    const __nv_bfloat16* erow = g_s + ((size_t)bh * T_ + rowg) * T_;

    float acc[2][6][4];
#pragma unroll
    for (int mt = 0; mt < 2; mt++)
#pragma unroll
        for (int nt = 0; nt < 6; nt++)
#pragma unroll
            for (int q = 0; q < 4; q++) acc[mt][nt][q] = 0.f;

    const int nit = min(4 * qt + 6, 64);   // k-chunks of 32 (= softmax coverage)
    union U8 { uint4 u; __nv_bfloat16 h[8]; };

    for (int it = 0; it < nit; it++) {
        const int k0 = it * 32;
        // stage P: own row, 32 e-values -> p = bf16(e * inv)
#pragma unroll
        for (int j = 0; j < 4; j++) {
            U8 pk; pk.u = *reinterpret_cast<const uint4*>(erow + k0 + j * 8);
            U8 po;
#pragma unroll
            for (int x = 0; x < 8; x++)
                po.h[x] = __float2bfloat16(__bfloat162float(pk.h[x]) * inv);
            *reinterpret_cast<uint4*>(Ps + tid * PITCH + j * 8) = po.u;
        }
        // stage V^T: 48 rows x 32 k
        for (int i = tid; i < 192; i += 128) {
            int rr = i >> 2, ss = (i & 3) * 8;
            *reinterpret_cast<uint4*>(Vs + rr * PITCH + ss) =
                *reinterpret_cast<const uint4*>(
                    g_vt + ((size_t)bh * D_ + rr) * T_ + k0 + ss);
        }
        __syncthreads();

#pragma unroll
        for (int ks = 0; ks < 2; ks++) {
            const int kb = ks * 16 + (lane & 3) * 2;
            uint32_t af[2][4];
#pragma unroll
            for (int mt = 0; mt < 2; mt++) {
                const __nv_bfloat16* ab = Ps + (wid * 32 + mt * 16 + (lane >> 2)) * PITCH + kb;
                af[mt][0] = *reinterpret_cast<const uint32_t*>(ab);
                af[mt][1] = *reinterpret_cast<const uint32_t*>(ab + 8 * PITCH);
                af[mt][2] = *reinterpret_cast<const uint32_t*>(ab + 8);
                af[mt][3] = *reinterpret_cast<const uint32_t*>(ab + 8 * PITCH + 8);
            }
            uint32_t bfr[6][2];
#pragma unroll
            for (int nt = 0; nt < 6; nt++) {
                const __nv_bfloat16* bb = Vs + (nt * 8 + (lane >> 2)) * PITCH + kb;
                bfr[nt][0] = *reinterpret_cast<const uint32_t*>(bb);
                bfr[nt][1] = *reinterpret_cast<const uint32_t*>(bb + 8);
            }
#pragma unroll
            for (int mt = 0; mt < 2; mt++)
#pragma unroll
                for (int nt = 0; nt < 6; nt++)
                    mma16816(acc[mt][nt], af[mt][0], af[mt][1], af[mt][2], af[mt][3],
                             bfr[nt][0], bfr[nt][1]);
        }
        __syncthreads();
    }

#pragma unroll
    for (int mt = 0; mt < 2; mt++) {
        int r0 = qt * 128 + wid * 32 + mt * 16 + (lane >> 2);
#pragma unroll
        for (int nt = 0; nt < 6; nt++) {
            int c0 = nt * 8 + (lane & 3) * 2;
#pragma unroll
            for (int half = 0; half < 2; half++) {
                int rr = r0 + half * 8;
                __nv_bfloat162 pk;
                pk.x = __float2bfloat16(acc[mt][nt][half * 2 + 0]);
                pk.y = __float2bfloat16(acc[mt][nt][half * 2 + 1]);
                *reinterpret_cast<__nv_bfloat162*>(
                    &g_y[(size_t)(b * T_ + rr) * C_ + h * D_ + c0]) = pk;
            }
        }
    }
}

// ---------------- launch ----------------
extern "C" void kernel_launch(void* const* d_in, const int* in_sizes, int n_in,
                              void* d_out, int out_size) {
    const void* x = nullptr; const void* w_attn = nullptr; const void* w_proj = nullptr;
    for (int i = 0; i < n_in; i++) {
        if      (in_sizes[i] == M_ * C_)  x      = d_in[i];
        else if (in_sizes[i] == C_ * C3_) w_attn = d_in[i];
        else if (in_sizes[i] == C_ * C_)  w_proj = d_in[i];
    }
    if (!x || !w_attn || !w_proj) { x = d_in[0]; w_attn = d_in[1]; w_proj = d_in[2]; }
    float* out = (float*)d_out;   // output dtype is float32

    __nv_bfloat16 *xb, *wa, *wp, *wat, *wpt, *qkv, *y;
    cudaGetSymbolAddress((void**)&xb,  g_xb);
    cudaGetSymbolAddress((void**)&wa,  g_wa);
    cudaGetSymbolAddress((void**)&wp,  g_wp);
    cudaGetSymbolAddress((void**)&wat, g_wat);
    cudaGetSymbolAddress((void**)&wpt, g_wpt);
    cudaGetSymbolAddress((void**)&qkv, g_qkv);
    cudaGetSymbolAddress((void**)&y,   g_y);

    const int nx  = M_ * C_;
    const int nwa = C_ * C3_;
    const int nwp = C_ * C_;

    detect_dtype<<<1, 256>>>(x,      0);
    detect_dtype<<<1, 256>>>(w_attn, 1);
    detect_dtype<<<1, 256>>>(w_proj, 2);

    cast_input4<<<(nx/4  + 255) / 256, 256>>>(x,      xb, nx/4,  0);
    cast_input4<<<(nwa/4 + 255) / 256, 256>>>(w_attn, wa, nwa/4, 1);
    cast_input4<<<(nwp/4 + 255) / 256, 256>>>(w_proj, wp, nwp/4, 2);

    {
        dim3 blk(32, 8);
        dim3 g1(C3_ / 32, C_ / 32);
        transpose_bf16<<<g1, blk>>>(wa, wat, C_, C3_);
        dim3 g2(C_ / 32, C_ / 32);
        transpose_bf16<<<g2, blk>>>(wp, wpt, C_, C_);
    }

    // QKV = Xb @ Wattn
    {
        dim3 grid((C3_ + 127) / 128, M_ / 128);
        gemm_hmma<0><<<grid, 256>>>(xb, wat, qkv, M_, C3_, C_);
    }

    // V^T per head
    {
        dim3 grid(T_ / 64, BH_);
        vt_kernel<<<grid, 256>>>();
    }

    // QK logits (causal tiles)
    {
        dim3 grid(T_ / 128, T_ / 128, BH_);
        qk_hmma<<<grid, 256>>>();
    }

    // softmax: s -> e in place, lb per row
    {
        softmax_es<<<BHT / 4, 128>>>();
    }

    // O = P*V via HMMA -> g_y
    {
        dim3 grid(T_ / 128, BH_);
        pv_hmma<<<grid, 128>>>();
    }

    // out(f32) = bf16round( Y @ Wproj )
    {
        dim3 grid((C_ + 127) / 128, M_ / 128);
        gemm_hmma<1><<<grid, 256>>>(y, wpt, out, M_, C_, C_);
    }
}